// round 2
// baseline (speedup 1.0000x reference)
#include <cuda_runtime.h>
#include <math.h>

// ---------------------------------------------------------------------------
// Problem constants
// ---------------------------------------------------------------------------
#define SQ     2048          // sequence length
#define DMODEL 4096          // model dim
#define NH     32            // heads
#define HD     128           // head dim
#define QKV_N  (3 * DMODEL)  // 12288

// ---------------------------------------------------------------------------
// Scratch (device globals; no allocations allowed)
// ---------------------------------------------------------------------------
__device__ float g_qkv[SQ * QKV_N];       // QKV GEMM output [s][12288]
__device__ float g_q[NH * SQ * HD];       // [h][s][d]
__device__ float g_k[NH * SQ * HD];
__device__ float g_v[NH * SQ * HD];
__device__ float g_ao[SQ * DMODEL];       // attention output [s][h*128+d]
__device__ float g_cos[SQ * 64];          // RoPE tables (fp64-accurate)
__device__ float g_sin[SQ * 64];

// ---------------------------------------------------------------------------
// RoPE table: one block per position, 64 threads (one per frequency)
// ---------------------------------------------------------------------------
__global__ __launch_bounds__(64)
void rope_table_kernel(const int* __restrict__ pos_ids,
                       float* __restrict__ cos_t, float* __restrict__ sin_t)
{
    const int s = blockIdx.x;
    const int j = threadIdx.x;
    // inv_freq = 10000^(-j/64), fp64 so our RoPE error << reference's fp32 error
    double invf  = exp2(-(double)j / 64.0 * 13.287712379549449);  // log2(10000)
    double theta = (double)pos_ids[s] * invf;
    cos_t[s * 64 + j] = (float)cos(theta);
    sin_t[s * 64 + j] = (float)sin(theta);
}

// ---------------------------------------------------------------------------
// SGEMM: C[M,N] = A[M,K] @ B[K,N], row-major, fp32
// 128x128 block, BK=8, 256 threads, 8x8 per-thread microtile
// ---------------------------------------------------------------------------
#define BM 128
#define BN 128
#define BK 8
#define TM 8
#define TN 8

__global__ __launch_bounds__(256)
void sgemm_kernel(const float* __restrict__ A, const float* __restrict__ B,
                  float* __restrict__ C, int M, int N, int K)
{
    __shared__ float As[BK][BM];
    __shared__ float Bs[BK][BN];

    const int bx = blockIdx.x;   // N tile
    const int by = blockIdx.y;   // M tile
    const int tid = threadIdx.x;

    // A-load mapping: 128 rows x 8 cols -> 1 float4 per thread
    const int arow = tid >> 1;            // 0..127
    const int acol = (tid & 1) * 4;       // 0 or 4
    // B-load mapping: 8 rows x 128 cols -> 1 float4 per thread
    const int brow = tid >> 5;            // 0..7
    const int bcol = (tid & 31) * 4;      // 0..124

    const int tx = tid & 15;              // 0..15
    const int ty = tid >> 4;              // 0..15

    const float* Aptr = A + (size_t)(by * BM) * K;
    const float* Bptr = B + bx * BN;

    float acc[TM][TN];
#pragma unroll
    for (int i = 0; i < TM; i++)
#pragma unroll
        for (int j = 0; j < TN; j++) acc[i][j] = 0.0f;

    for (int k0 = 0; k0 < K; k0 += BK) {
        float4 av = *(const float4*)(Aptr + (size_t)arow * K + k0 + acol);
        As[acol + 0][arow] = av.x;
        As[acol + 1][arow] = av.y;
        As[acol + 2][arow] = av.z;
        As[acol + 3][arow] = av.w;
        float4 bv = *(const float4*)(Bptr + (size_t)(k0 + brow) * N + bcol);
        *(float4*)&Bs[brow][bcol] = bv;
        __syncthreads();

#pragma unroll
        for (int k = 0; k < BK; k++) {
            float a_frag[TM], b_frag[TN];
#pragma unroll
            for (int i = 0; i < TM; i++) a_frag[i] = As[k][ty * TM + i];
#pragma unroll
            for (int j = 0; j < TN; j++) b_frag[j] = Bs[k][tx * TN + j];
#pragma unroll
            for (int i = 0; i < TM; i++)
#pragma unroll
                for (int j = 0; j < TN; j++)
                    acc[i][j] += a_frag[i] * b_frag[j];
        }
        __syncthreads();
    }

    float* Cptr = C + (size_t)(by * BM + ty * TM) * N + bx * BN + tx * TN;
#pragma unroll
    for (int i = 0; i < TM; i++) {
        float4 c0 = make_float4(acc[i][0], acc[i][1], acc[i][2], acc[i][3]);
        float4 c1 = make_float4(acc[i][4], acc[i][5], acc[i][6], acc[i][7]);
        *(float4*)(Cptr + (size_t)i * N)     = c0;
        *(float4*)(Cptr + (size_t)i * N + 4) = c1;
    }
}

// ---------------------------------------------------------------------------
// De-interleave QKV + RoPE
// grid (NH, SQ), block HD threads. qkv layout: [s][d*3 + {0,1,2}]
// ---------------------------------------------------------------------------
__global__ __launch_bounds__(HD)
void rope_kernel(const float* __restrict__ qkv,
                 const float* __restrict__ cos_t, const float* __restrict__ sin_t,
                 float* __restrict__ Q, float* __restrict__ K, float* __restrict__ V)
{
    const int h = blockIdx.x;
    const int s = blockIdx.y;
    const int i = threadIdx.x;

    __shared__ float qs[HD], ks[HD];

    const size_t base = (size_t)s * QKV_N + 3 * (h * HD);
    float qv = qkv[base + 3 * i + 0];
    float kv = qkv[base + 3 * i + 1];
    float vv = qkv[base + 3 * i + 2];
    qs[i] = qv;
    ks[i] = kv;
    __syncthreads();

    const int j = i & 63;
    float c  = cos_t[s * 64 + j];
    float sn = sin_t[s * 64 + j];

    float qr = (i < 64) ? -qs[i + 64] : qs[i - 64];
    float kr = (i < 64) ? -ks[i + 64] : ks[i - 64];

    const size_t o = ((size_t)h * SQ + s) * HD + i;
    Q[o] = qv * c + qr * sn;
    K[o] = kv * c + kr * sn;
    V[o] = vv;
}

// ---------------------------------------------------------------------------
// Flash attention (causal), fp32.
// grid (SQ/64, NH), 256 threads (8 warps). Warp w handles rows w*8..w*8+7.
// Lane handles keys (lane, lane+32) in score phase; d-chunk lane*4..+3 in PV.
// ---------------------------------------------------------------------------
#define BQ 64
#define BKEY 64
#define KT_PITCH 65   // transposed K pitch -> conflict-free

#define SM_QS   0                                  // 64*128 floats
#define SM_KT   (SM_QS + BQ * HD)                  // 128*65
#define SM_VS   (SM_KT + HD * KT_PITCH)            // 64*128
#define SM_PS   (SM_VS + BKEY * HD)                // 64 rows * 64 keys
#define FLASH_SMEM_FLOATS (SM_PS + BQ * BKEY)
#define FLASH_SMEM_BYTES (FLASH_SMEM_FLOATS * 4)

__global__ __launch_bounds__(256)
void flash_kernel(const float* __restrict__ Q, const float* __restrict__ K,
                  const float* __restrict__ V, float* __restrict__ O)
{
    extern __shared__ float sm[];
    float* Qs  = sm + SM_QS;
    float* KsT = sm + SM_KT;
    float* Vs  = sm + SM_VS;
    float* Ps  = sm + SM_PS;

    const int qb   = blockIdx.x;
    const int h    = blockIdx.y;
    const int tid  = threadIdx.x;
    const int w    = tid >> 5;
    const int lane = tid & 31;

    // Load Q tile [64][128]
    const float* Qg = Q + ((size_t)h * SQ + qb * BQ) * HD;
    for (int idx = tid * 4; idx < BQ * HD; idx += 256 * 4)
        *(float4*)(Qs + idx) = *(const float4*)(Qg + idx);

    float m[8], l[8], acc[8][4];
#pragma unroll
    for (int r = 0; r < 8; r++) {
        m[r] = -1e30f; l[r] = 0.0f;
        acc[r][0] = acc[r][1] = acc[r][2] = acc[r][3] = 0.0f;
    }

    const float scale = 0.08838834764831845f;  // 1/sqrt(128)

    for (int kb = 0; kb <= qb; kb++) {
        __syncthreads();  // protect previous-iter smem reads (and Q on iter 0)

        const float* Kg = K + ((size_t)h * SQ + kb * BKEY) * HD;
        const float* Vg = V + ((size_t)h * SQ + kb * BKEY) * HD;
        // K transposed: KsT[d][j]
        for (int idx = tid * 4; idx < BKEY * HD; idx += 256 * 4) {
            int j = idx >> 7, d = idx & 127;
            float4 kv4 = *(const float4*)(Kg + idx);
            KsT[(d + 0) * KT_PITCH + j] = kv4.x;
            KsT[(d + 1) * KT_PITCH + j] = kv4.y;
            KsT[(d + 2) * KT_PITCH + j] = kv4.z;
            KsT[(d + 3) * KT_PITCH + j] = kv4.w;
        }
        for (int idx = tid * 4; idx < BKEY * HD; idx += 256 * 4)
            *(float4*)(Vs + idx) = *(const float4*)(Vg + idx);
        __syncthreads();

        // ---- scores: s[r][k] for keys j0=lane, j1=lane+32 ----
        float s0[8], s1[8];
#pragma unroll
        for (int r = 0; r < 8; r++) { s0[r] = 0.0f; s1[r] = 0.0f; }

#pragma unroll 8
        for (int d = 0; d < HD; d++) {
            float k0 = KsT[d * KT_PITCH + lane];
            float k1 = KsT[d * KT_PITCH + lane + 32];
            const float* qrow = Qs + (w * 8) * HD + d;
#pragma unroll
            for (int r = 0; r < 8; r++) {
                float qv = qrow[r * HD];
                s0[r] += qv * k0;
                s1[r] += qv * k1;
            }
        }

        const bool diag = (kb == qb);
        const int j0 = kb * BKEY + lane;
        const int j1 = j0 + 32;

#pragma unroll
        for (int r = 0; r < 8; r++) {
            const int qg = qb * BQ + w * 8 + r;
            float v0 = s0[r] * scale;
            float v1 = s1[r] * scale;
            if (diag) {
                if (j0 > qg) v0 = -1e30f;
                if (j1 > qg) v1 = -1e30f;
            }
            float mx = fmaxf(v0, v1);
#pragma unroll
            for (int off = 16; off; off >>= 1)
                mx = fmaxf(mx, __shfl_xor_sync(0xFFFFFFFFu, mx, off));
            float mn = fmaxf(m[r], mx);
            float p0 = __expf(v0 - mn);
            float p1 = __expf(v1 - mn);
            float corr = __expf(m[r] - mn);
            m[r] = mn;
            float ps = p0 + p1;
#pragma unroll
            for (int off = 16; off; off >>= 1)
                ps += __shfl_xor_sync(0xFFFFFFFFu, ps, off);
            l[r] = l[r] * corr + ps;
            acc[r][0] *= corr; acc[r][1] *= corr;
            acc[r][2] *= corr; acc[r][3] *= corr;
            Ps[(w * 8 + r) * BKEY + lane]      = p0;
            Ps[(w * 8 + r) * BKEY + lane + 32] = p1;
        }
        __syncwarp();

        // ---- PV: lane owns d-chunk lane*4..lane*4+3 ----
#pragma unroll 2
        for (int jj = 0; jj < BKEY; jj++) {
            float4 vv = *(float4*)(Vs + jj * HD + lane * 4);
            const float* prow = Ps + (w * 8) * BKEY + jj;
#pragma unroll
            for (int r = 0; r < 8; r++) {
                float p = prow[r * BKEY];
                acc[r][0] += p * vv.x;
                acc[r][1] += p * vv.y;
                acc[r][2] += p * vv.z;
                acc[r][3] += p * vv.w;
            }
        }
    }

    // epilogue: O[s][h*128 + d]
#pragma unroll
    for (int r = 0; r < 8; r++) {
        float inv = 1.0f / l[r];
        float4 o4 = make_float4(acc[r][0] * inv, acc[r][1] * inv,
                                acc[r][2] * inv, acc[r][3] * inv);
        size_t off = (size_t)(qb * BQ + w * 8 + r) * DMODEL + h * HD + lane * 4;
        *(float4*)(O + off) = o4;
    }
}

// ---------------------------------------------------------------------------
// kernel_launch
// inputs: 0 hidden_states f32 [1,2048,4096], 1 attention_mask (unused),
//         2 position_ids i32 [1,2048], 3 Wqkv f32 [4096,12288], 4 Wo f32 [4096,4096]
// output: f32 [1,2048,4096]
// ---------------------------------------------------------------------------
extern "C" void kernel_launch(void* const* d_in, const int* in_sizes, int n_in,
                              void* d_out, int out_size)
{
    const float* X    = (const float*)d_in[0];
    const int*   pos  = (const int*)d_in[2];
    const float* Wqkv = (const float*)d_in[3];
    const float* Wo   = (const float*)d_in[4];
    float* out = (float*)d_out;

    float *qkv, *q, *k, *v, *ao, *cost, *sint;
    cudaGetSymbolAddress((void**)&qkv,  g_qkv);
    cudaGetSymbolAddress((void**)&q,    g_q);
    cudaGetSymbolAddress((void**)&k,    g_k);
    cudaGetSymbolAddress((void**)&v,    g_v);
    cudaGetSymbolAddress((void**)&ao,   g_ao);
    cudaGetSymbolAddress((void**)&cost, g_cos);
    cudaGetSymbolAddress((void**)&sint, g_sin);

    cudaFuncSetAttribute(flash_kernel, cudaFuncAttributeMaxDynamicSharedMemorySize,
                         FLASH_SMEM_BYTES);

    // 0) RoPE tables (fp64-accurate, tiny)
    rope_table_kernel<<<SQ, 64>>>(pos, cost, sint);
    // 1) QKV projection
    sgemm_kernel<<<dim3(QKV_N / BN, SQ / BM), 256>>>(X, Wqkv, qkv, SQ, QKV_N, DMODEL);
    // 2) de-interleave + RoPE
    rope_kernel<<<dim3(NH, SQ), HD>>>(qkv, cost, sint, q, k, v);
    // 3) causal flash attention
    flash_kernel<<<dim3(SQ / BQ, NH), 256, FLASH_SMEM_BYTES>>>(q, k, v, ao);
    // 4) output projection
    sgemm_kernel<<<dim3(DMODEL / BN, SQ / BM), 256>>>(ao, Wo, out, SQ, DMODEL, DMODEL);
}

// round 3
// speedup vs baseline: 2.1765x; 2.1765x over previous
#include <cuda_runtime.h>
#include <cuda_bf16.h>
#include <math.h>
#include <stdint.h>

// ---------------------------------------------------------------------------
// Problem constants
// ---------------------------------------------------------------------------
#define SQ     2048
#define DMODEL 4096
#define NH     32
#define HD     128
#define QKV_N  (3 * DMODEL)  // 12288

typedef __nv_bfloat16 bf16;

// ---------------------------------------------------------------------------
// Scratch (device globals; allocations are forbidden)
// ---------------------------------------------------------------------------
__device__ float g_qkv[SQ * QKV_N];
__device__ float g_q[NH * SQ * HD];
__device__ float g_k[NH * SQ * HD];
__device__ float g_v[NH * SQ * HD];
__device__ float g_ao[SQ * DMODEL];
__device__ float g_cos[SQ * 64];
__device__ float g_sin[SQ * 64];

__device__ bf16 g_xh[SQ * DMODEL],      g_xl[SQ * DMODEL];
__device__ bf16 g_wqkvh[DMODEL * QKV_N], g_wqkvl[DMODEL * QKV_N];
__device__ bf16 g_woh[DMODEL * DMODEL],  g_wol[DMODEL * DMODEL];
__device__ bf16 g_aoh[SQ * DMODEL],      g_aol[SQ * DMODEL];

// ---------------------------------------------------------------------------
// fp32 -> (bf16 hi, bf16 lo) split
// ---------------------------------------------------------------------------
__global__ __launch_bounds__(256)
void split_kernel(const float* __restrict__ in, bf16* __restrict__ hi,
                  bf16* __restrict__ lo, int n4)
{
    int i = blockIdx.x * blockDim.x + threadIdx.x;
    if (i >= n4) return;
    float4 v = ((const float4*)in)[i];
    float f[4] = {v.x, v.y, v.z, v.w};
    bf16 hv[4], lv[4];
#pragma unroll
    for (int j = 0; j < 4; j++) {
        bf16 h = __float2bfloat16_rn(f[j]);
        hv[j] = h;
        lv[j] = __float2bfloat16_rn(f[j] - __bfloat162float(h));
    }
    *((uint2*)hi + i) = *(uint2*)hv;
    *((uint2*)lo + i) = *(uint2*)lv;
}

// ---------------------------------------------------------------------------
// RoPE tables (fp64-accurate)
// ---------------------------------------------------------------------------
__global__ __launch_bounds__(64)
void rope_table_kernel(const int* __restrict__ pos_ids,
                       float* __restrict__ cos_t, float* __restrict__ sin_t)
{
    const int s = blockIdx.x;
    const int j = threadIdx.x;
    double invf  = exp2(-(double)j / 64.0 * 13.287712379549449);  // log2(10000)
    double theta = (double)pos_ids[s] * invf;
    cos_t[s * 64 + j] = (float)cos(theta);
    sin_t[s * 64 + j] = (float)sin(theta);
}

// ---------------------------------------------------------------------------
// bf16-split GEMM: C[M,N] = A[M,K] @ B[K,N] (fp32-quality via Ah*Bh+Ah*Bl+Al*Bh)
// 128x128 CTA tile, BK=32, 256 threads (2x4 warps, 64x32 warp tile),
// mma.sync.m16n8k16.bf16, 2-stage cp.async pipeline.
// ---------------------------------------------------------------------------
#define GBM 128
#define GBN 128
#define GBK 32

// smem layout (bytes): A pitch 40 bf16 (conflict-free ldsm), B pitch 136 bf16
#define A_ST   10240                 // 128*40*2 per stage per array
#define B_ST    8704                 // 32*136*2
#define AH_OFF     0
#define AL_OFF (2 * A_ST)            // 20480
#define BH_OFF (4 * A_ST)            // 40960
#define BL_OFF (BH_OFF + 2 * B_ST)   // 58368
#define GEMM_SMEM (BL_OFF + 2 * B_ST)  // 75776

__device__ __forceinline__ void cp16(uint32_t dst, const void* src) {
    asm volatile("cp.async.cg.shared.global [%0], [%1], 16;\n" :: "r"(dst), "l"(src));
}
__device__ __forceinline__ void ldsm4(uint32_t* r, uint32_t a) {
    asm volatile("ldmatrix.sync.aligned.m8n8.x4.shared.b16 {%0,%1,%2,%3},[%4];"
                 : "=r"(r[0]), "=r"(r[1]), "=r"(r[2]), "=r"(r[3]) : "r"(a));
}
__device__ __forceinline__ void ldsm4t(uint32_t* r, uint32_t a) {
    asm volatile("ldmatrix.sync.aligned.m8n8.x4.trans.shared.b16 {%0,%1,%2,%3},[%4];"
                 : "=r"(r[0]), "=r"(r[1]), "=r"(r[2]), "=r"(r[3]) : "r"(a));
}
__device__ __forceinline__ void mma16816(float* c, const uint32_t* a,
                                         uint32_t b0, uint32_t b1) {
    asm volatile(
        "mma.sync.aligned.m16n8k16.row.col.f32.bf16.bf16.f32 "
        "{%0,%1,%2,%3},{%4,%5,%6,%7},{%8,%9},{%0,%1,%2,%3};"
        : "+f"(c[0]), "+f"(c[1]), "+f"(c[2]), "+f"(c[3])
        : "r"(a[0]), "r"(a[1]), "r"(a[2]), "r"(a[3]), "r"(b0), "r"(b1));
}

__global__ __launch_bounds__(256, 1)
void gemm_bf16split_kernel(const bf16* __restrict__ Ah, const bf16* __restrict__ Al,
                           const bf16* __restrict__ Bh, const bf16* __restrict__ Bl,
                           float* __restrict__ C, int M, int N, int K)
{
    extern __shared__ char smem[];
    const uint32_t sb = (uint32_t)__cvta_generic_to_shared(smem);

    const int tid  = threadIdx.x;
    const int wid  = tid >> 5;
    const int lane = tid & 31;
    const int m0 = blockIdx.y * GBM;
    const int n0 = blockIdx.x * GBN;
    const int m_warp = (wid & 1) * 64;
    const int n_warp = (wid >> 1) * 32;
    const int lrow  = lane & 15;
    const int lcol8 = (lane >> 4) * 8;

    float c[4][4][4];
#pragma unroll
    for (int mt = 0; mt < 4; mt++)
#pragma unroll
        for (int nt = 0; nt < 4; nt++)
#pragma unroll
            for (int j = 0; j < 4; j++) c[mt][nt][j] = 0.0f;

    const int NT = K / GBK;

    // stage loader
    auto load_stage = [&](int st, int kt) {
        const int k0 = kt * GBK;
        // A tiles: 128 rows x 32 bf16 = 4 x 16B chunks per row
#pragma unroll
        for (int rep = 0; rep < 2; rep++) {
            int i = tid + rep * 256;        // 0..511
            int row = i >> 2, ch = i & 3;
            uint32_t da = sb + AH_OFF + st * A_ST + (uint32_t)(row * 40 + ch * 8) * 2;
            size_t   sa = (size_t)(m0 + row) * K + k0 + ch * 8;
            cp16(da,                     Ah + sa);
            cp16(da + (AL_OFF - AH_OFF), Al + sa);
        }
        // B tiles: 32 rows x 128 bf16 = 16 x 16B chunks per row
#pragma unroll
        for (int rep = 0; rep < 2; rep++) {
            int i = tid + rep * 256;        // 0..511
            int row = i >> 4, ch = i & 15;
            uint32_t db = sb + BH_OFF + st * B_ST + (uint32_t)(row * 136 + ch * 8) * 2;
            size_t   sbg = (size_t)(k0 + row) * N + n0 + ch * 8;
            cp16(db,                     Bh + sbg);
            cp16(db + (BL_OFF - BH_OFF), Bl + sbg);
        }
        asm volatile("cp.async.commit_group;\n" ::);
    };

    load_stage(0, 0);

    for (int kt = 0; kt < NT; kt++) {
        const int st = kt & 1;
        asm volatile("cp.async.wait_group 0;\n" ::);
        __syncthreads();
        if (kt + 1 < NT) load_stage(st ^ 1, kt + 1);

#pragma unroll
        for (int ks = 0; ks < GBK; ks += 16) {
            uint32_t ah[4][4], al[4][4], bh[2][4], bl[2][4];
#pragma unroll
            for (int mt = 0; mt < 4; mt++) {
                uint32_t ad = sb + AH_OFF + st * A_ST +
                    (uint32_t)((m_warp + mt * 16 + lrow) * 40 + ks + lcol8) * 2;
                ldsm4(ah[mt], ad);
                ldsm4(al[mt], ad + (AL_OFF - AH_OFF));
            }
#pragma unroll
            for (int np = 0; np < 2; np++) {
                uint32_t bd = sb + BH_OFF + st * B_ST +
                    (uint32_t)((ks + lrow) * 136 + n_warp + np * 16 + lcol8) * 2;
                ldsm4t(bh[np], bd);
                ldsm4t(bl[np], bd + (BL_OFF - BH_OFF));
            }
#pragma unroll
            for (int mt = 0; mt < 4; mt++)
#pragma unroll
                for (int nt = 0; nt < 4; nt++) {
                    const int np = nt >> 1, hf = (nt & 1) * 2;
                    mma16816(c[mt][nt], ah[mt], bh[np][hf], bh[np][hf + 1]);
                    mma16816(c[mt][nt], ah[mt], bl[np][hf], bl[np][hf + 1]);
                    mma16816(c[mt][nt], al[mt], bh[np][hf], bh[np][hf + 1]);
                }
        }
        __syncthreads();
    }

    // epilogue: C frag layout m16n8: c0,c1 @ (lane/4, (lane%4)*2), c2,c3 @ row+8
#pragma unroll
    for (int mt = 0; mt < 4; mt++) {
        const int row = m0 + m_warp + mt * 16 + (lane >> 2);
#pragma unroll
        for (int nt = 0; nt < 4; nt++) {
            const int col = n0 + n_warp + nt * 8 + (lane & 3) * 2;
            float2* p0 = (float2*)(C + (size_t)row * N + col);
            float2* p1 = (float2*)(C + (size_t)(row + 8) * N + col);
            *p0 = make_float2(c[mt][nt][0], c[mt][nt][1]);
            *p1 = make_float2(c[mt][nt][2], c[mt][nt][3]);
        }
    }
}

// ---------------------------------------------------------------------------
// De-interleave QKV + RoPE
// ---------------------------------------------------------------------------
__global__ __launch_bounds__(HD)
void rope_kernel(const float* __restrict__ qkv,
                 const float* __restrict__ cos_t, const float* __restrict__ sin_t,
                 float* __restrict__ Q, float* __restrict__ K, float* __restrict__ V)
{
    const int h = blockIdx.x;
    const int s = blockIdx.y;
    const int i = threadIdx.x;

    __shared__ float qs[HD], ks[HD];

    const size_t base = (size_t)s * QKV_N + 3 * (h * HD);
    float qv = qkv[base + 3 * i + 0];
    float kv = qkv[base + 3 * i + 1];
    float vv = qkv[base + 3 * i + 2];
    qs[i] = qv;
    ks[i] = kv;
    __syncthreads();

    const int j = i & 63;
    float c  = cos_t[s * 64 + j];
    float sn = sin_t[s * 64 + j];

    float qr = (i < 64) ? -qs[i + 64] : qs[i - 64];
    float kr = (i < 64) ? -ks[i + 64] : ks[i - 64];

    const size_t o = ((size_t)h * SQ + s) * HD + i;
    Q[o] = qv * c + qr * sn;
    K[o] = kv * c + kr * sn;
    V[o] = vv;
}

// ---------------------------------------------------------------------------
// Flash attention (causal), fp32 (unchanged from passing round)
// ---------------------------------------------------------------------------
#define BQ 64
#define BKEY 64
#define KT_PITCH 65

#define SM_QS   0
#define SM_KT   (SM_QS + BQ * HD)
#define SM_VS   (SM_KT + HD * KT_PITCH)
#define SM_PS   (SM_VS + BKEY * HD)
#define FLASH_SMEM_FLOATS (SM_PS + BQ * BKEY)
#define FLASH_SMEM_BYTES (FLASH_SMEM_FLOATS * 4)

__global__ __launch_bounds__(256)
void flash_kernel(const float* __restrict__ Q, const float* __restrict__ K,
                  const float* __restrict__ V, float* __restrict__ O)
{
    extern __shared__ float sm[];
    float* Qs  = sm + SM_QS;
    float* KsT = sm + SM_KT;
    float* Vs  = sm + SM_VS;
    float* Ps  = sm + SM_PS;

    const int qb   = blockIdx.x;
    const int h    = blockIdx.y;
    const int tid  = threadIdx.x;
    const int w    = tid >> 5;
    const int lane = tid & 31;

    const float* Qg = Q + ((size_t)h * SQ + qb * BQ) * HD;
    for (int idx = tid * 4; idx < BQ * HD; idx += 256 * 4)
        *(float4*)(Qs + idx) = *(const float4*)(Qg + idx);

    float m[8], l[8], acc[8][4];
#pragma unroll
    for (int r = 0; r < 8; r++) {
        m[r] = -1e30f; l[r] = 0.0f;
        acc[r][0] = acc[r][1] = acc[r][2] = acc[r][3] = 0.0f;
    }

    const float scale = 0.08838834764831845f;

    for (int kb = 0; kb <= qb; kb++) {
        __syncthreads();

        const float* Kg = K + ((size_t)h * SQ + kb * BKEY) * HD;
        const float* Vg = V + ((size_t)h * SQ + kb * BKEY) * HD;
        for (int idx = tid * 4; idx < BKEY * HD; idx += 256 * 4) {
            int j = idx >> 7, d = idx & 127;
            float4 kv4 = *(const float4*)(Kg + idx);
            KsT[(d + 0) * KT_PITCH + j] = kv4.x;
            KsT[(d + 1) * KT_PITCH + j] = kv4.y;
            KsT[(d + 2) * KT_PITCH + j] = kv4.z;
            KsT[(d + 3) * KT_PITCH + j] = kv4.w;
        }
        for (int idx = tid * 4; idx < BKEY * HD; idx += 256 * 4)
            *(float4*)(Vs + idx) = *(const float4*)(Vg + idx);
        __syncthreads();

        float s0[8], s1[8];
#pragma unroll
        for (int r = 0; r < 8; r++) { s0[r] = 0.0f; s1[r] = 0.0f; }

#pragma unroll 8
        for (int d = 0; d < HD; d++) {
            float k0 = KsT[d * KT_PITCH + lane];
            float k1 = KsT[d * KT_PITCH + lane + 32];
            const float* qrow = Qs + (w * 8) * HD + d;
#pragma unroll
            for (int r = 0; r < 8; r++) {
                float qv = qrow[r * HD];
                s0[r] += qv * k0;
                s1[r] += qv * k1;
            }
        }

        const bool diag = (kb == qb);
        const int j0 = kb * BKEY + lane;
        const int j1 = j0 + 32;

#pragma unroll
        for (int r = 0; r < 8; r++) {
            const int qg = qb * BQ + w * 8 + r;
            float v0 = s0[r] * scale;
            float v1 = s1[r] * scale;
            if (diag) {
                if (j0 > qg) v0 = -1e30f;
                if (j1 > qg) v1 = -1e30f;
            }
            float mx = fmaxf(v0, v1);
#pragma unroll
            for (int off = 16; off; off >>= 1)
                mx = fmaxf(mx, __shfl_xor_sync(0xFFFFFFFFu, mx, off));
            float mn = fmaxf(m[r], mx);
            float p0 = __expf(v0 - mn);
            float p1 = __expf(v1 - mn);
            float corr = __expf(m[r] - mn);
            m[r] = mn;
            float ps = p0 + p1;
#pragma unroll
            for (int off = 16; off; off >>= 1)
                ps += __shfl_xor_sync(0xFFFFFFFFu, ps, off);
            l[r] = l[r] * corr + ps;
            acc[r][0] *= corr; acc[r][1] *= corr;
            acc[r][2] *= corr; acc[r][3] *= corr;
            Ps[(w * 8 + r) * BKEY + lane]      = p0;
            Ps[(w * 8 + r) * BKEY + lane + 32] = p1;
        }
        __syncwarp();

#pragma unroll 2
        for (int jj = 0; jj < BKEY; jj++) {
            float4 vv = *(float4*)(Vs + jj * HD + lane * 4);
            const float* prow = Ps + (w * 8) * BKEY + jj;
#pragma unroll
            for (int r = 0; r < 8; r++) {
                float p = prow[r * BKEY];
                acc[r][0] += p * vv.x;
                acc[r][1] += p * vv.y;
                acc[r][2] += p * vv.z;
                acc[r][3] += p * vv.w;
            }
        }
    }

#pragma unroll
    for (int r = 0; r < 8; r++) {
        float inv = 1.0f / l[r];
        float4 o4 = make_float4(acc[r][0] * inv, acc[r][1] * inv,
                                acc[r][2] * inv, acc[r][3] * inv);
        size_t off = (size_t)(qb * BQ + w * 8 + r) * DMODEL + h * HD + lane * 4;
        *(float4*)(O + off) = o4;
    }
}

// ---------------------------------------------------------------------------
// kernel_launch
// ---------------------------------------------------------------------------
extern "C" void kernel_launch(void* const* d_in, const int* in_sizes, int n_in,
                              void* d_out, int out_size)
{
    const float* X    = (const float*)d_in[0];
    const int*   pos  = (const int*)d_in[2];
    const float* Wqkv = (const float*)d_in[3];
    const float* Wo   = (const float*)d_in[4];
    float* out = (float*)d_out;

    float *qkv, *q, *k, *v, *ao, *cost, *sint;
    bf16 *xh, *xl, *wqh, *wql, *woh, *wol, *aoh, *aol;
    cudaGetSymbolAddress((void**)&qkv,  g_qkv);
    cudaGetSymbolAddress((void**)&q,    g_q);
    cudaGetSymbolAddress((void**)&k,    g_k);
    cudaGetSymbolAddress((void**)&v,    g_v);
    cudaGetSymbolAddress((void**)&ao,   g_ao);
    cudaGetSymbolAddress((void**)&cost, g_cos);
    cudaGetSymbolAddress((void**)&sint, g_sin);
    cudaGetSymbolAddress((void**)&xh,   g_xh);
    cudaGetSymbolAddress((void**)&xl,   g_xl);
    cudaGetSymbolAddress((void**)&wqh,  g_wqkvh);
    cudaGetSymbolAddress((void**)&wql,  g_wqkvl);
    cudaGetSymbolAddress((void**)&woh,  g_woh);
    cudaGetSymbolAddress((void**)&wol,  g_wol);
    cudaGetSymbolAddress((void**)&aoh,  g_aoh);
    cudaGetSymbolAddress((void**)&aol,  g_aol);

    cudaFuncSetAttribute(flash_kernel, cudaFuncAttributeMaxDynamicSharedMemorySize,
                         FLASH_SMEM_BYTES);
    cudaFuncSetAttribute(gemm_bf16split_kernel,
                         cudaFuncAttributeMaxDynamicSharedMemorySize, GEMM_SMEM);

    // 0) RoPE tables + input/weight splits
    rope_table_kernel<<<SQ, 64>>>(pos, cost, sint);
    split_kernel<<<(SQ * DMODEL / 4 + 255) / 256, 256>>>(X, xh, xl, SQ * DMODEL / 4);
    split_kernel<<<(DMODEL * QKV_N / 4 + 255) / 256, 256>>>(Wqkv, wqh, wql,
                                                            DMODEL * QKV_N / 4);
    split_kernel<<<(DMODEL * DMODEL / 4 + 255) / 256, 256>>>(Wo, woh, wol,
                                                             DMODEL * DMODEL / 4);
    // 1) QKV projection (tensor cores, bf16 split)
    gemm_bf16split_kernel<<<dim3(QKV_N / GBN, SQ / GBM), 256, GEMM_SMEM>>>(
        xh, xl, wqh, wql, qkv, SQ, QKV_N, DMODEL);
    // 2) de-interleave + RoPE
    rope_kernel<<<dim3(NH, SQ), HD>>>(qkv, cost, sint, q, k, v);
    // 3) causal flash attention
    flash_kernel<<<dim3(SQ / BQ, NH), 256, FLASH_SMEM_BYTES>>>(q, k, v, ao);
    // 4) split attention output, then O-projection (tensor cores)
    split_kernel<<<(SQ * DMODEL / 4 + 255) / 256, 256>>>(ao, aoh, aol, SQ * DMODEL / 4);
    gemm_bf16split_kernel<<<dim3(DMODEL / GBN, SQ / GBM), 256, GEMM_SMEM>>>(
        aoh, aol, woh, wol, out, SQ, DMODEL, DMODEL);
}